// round 1
// baseline (speedup 1.0000x reference)
#include <cuda_runtime.h>
#include <math.h>

#define NC   2000   // codes
#define EV   32     // visits
#define DD   128    // embedding dim
#define HD   256    // hidden dim
#define NOUT 1000
#define NB   16     // batch
#define PAD  128    // max nnz per adj row/col
#define EPSF 1e-12f

// ---------------- scratch (device globals; no allocation) ----------------
static __device__ float d_icd[NC*DD];
static __device__ float d_buf[NC*DD];
static __device__ float d_EWh[NC*HD];
static __device__ float d_EWc[NC*HD];
static __device__ float d_IWi[NC*HD];

static __device__ int   d_rowcnt[NC];
static __device__ int   d_rowidx[NC*PAD];
static __device__ float d_rowval[NC*PAD];
static __device__ int   d_colcnt[NC];
static __device__ int   d_colidx[NC*PAD];
static __device__ float d_colval[NC*PAD];

static __device__ unsigned d_vmask[NB*NC];
static __device__ unsigned d_smask[NB*NC];
static __device__ unsigned d_dmask[NB*NC];
static __device__ float d_Dv[NB*NC];
static __device__ float d_Dvinv[NB*NC];
static __device__ int d_act[NB*NC];  static __device__ int d_actn[NB];
static __device__ int d_Sl[NB*NC];   static __device__ int d_Sn[NB];
static __device__ int d_Tl[NB*NC];   static __device__ int d_Tn[NB];
static __device__ float d_rowsum[NB*NC];
static __device__ float d_colsum[NB*NC];
static __device__ float d_tph[NB*EV*HD];
static __device__ float d_tpi[NB*EV*HD];
static __device__ float d_yw[(size_t)NB*NC*HD];  // A @ (emb@W_c), rows indexed by S-position
static __device__ float d_zr[(size_t)NB*NC*HD];  // relu(A^T @ yw + b_c), rows by T-position
static __device__ float d_eh[NB*HD], d_ec[NB*HD], d_ei[NB*HD];
static __device__ float d_res[NB*HD];

__device__ __forceinline__ float warp_sum(float v){
  #pragma unroll
  for (int o=16;o>0;o>>=1) v += __shfl_down_sync(0xffffffffu, v, o);
  return v;
}

// ---------------- init: zero the atomically-accumulated colsum ----------------
__global__ void k_init(){
  int t = blockIdx.x*blockDim.x + threadIdx.x;
  if (t < NB*NC) d_colsum[t] = 0.f;
}

// ---------------- CSR of adj (warp per row, deterministic ascending order) ----
__global__ void k_csr_rows(const float* __restrict__ adj){
  int w = threadIdx.x >> 5, lane = threadIdx.x & 31;
  int r = blockIdx.x*32 + w;
  if (r >= NC) return;
  int cnt = 0;
  for (int jt=0; jt<NC; jt+=32){
    int j = jt + lane;
    float v = (j < NC) ? adj[(size_t)r*NC + j] : 0.f;
    unsigned m = __ballot_sync(0xffffffffu, v != 0.f);
    if (v != 0.f){
      int pos = cnt + __popc(m & ((1u<<lane)-1u));
      if (pos < PAD){ d_rowidx[r*PAD+pos] = j; d_rowval[r*PAD+pos] = v; }
    }
    cnt += __popc(m);
  }
  if (lane == 0) d_rowcnt[r] = (cnt < PAD) ? cnt : PAD;
}

// ---------------- CSC of adj (thread per column, coalesced, deterministic) ----
__global__ void k_csr_cols(const float* __restrict__ adj){
  int j = blockIdx.x*blockDim.x + threadIdx.x;
  if (j >= NC) return;
  int cnt = 0;
  for (int i=0; i<NC; i++){
    float v = adj[(size_t)i*NC + j];
    if (v != 0.f && cnt < PAD){ d_colidx[j*PAD+cnt] = i; d_colval[j*PAD+cnt] = v; cnt++; }
  }
  d_colcnt[j] = cnt;
}

// ---------------- sparse y = adj @ x -------------------------------------------
__global__ void k_spmm_rows(const float* __restrict__ emb, int use_icd){
  const float* src = use_icd ? d_icd : emb;
  int i = blockIdx.x, d = threadIdx.x;
  int cnt = d_rowcnt[i];
  const int*   idx = d_rowidx + i*PAD;
  const float* val = d_rowval + i*PAD;
  float acc = 0.f;
  for (int p=0; p<cnt; p++) acc += val[p]*src[(size_t)idx[p]*DD + d];
  d_buf[i*DD + d] = acc;
}

// ---------------- x = LN(adj.T @ buf) -------------------------------------------
__global__ void k_spmm_cols_ln(const float* __restrict__ g, const float* __restrict__ b){
  int j = blockIdx.x, d = threadIdx.x;
  int cnt = d_colcnt[j];
  const int*   idx = d_colidx + j*PAD;
  const float* val = d_colval + j*PAD;
  float acc = 0.f;
  for (int p=0; p<cnt; p++) acc += val[p]*d_buf[(size_t)idx[p]*DD + d];
  __shared__ float sred[DD];
  sred[d] = acc; __syncthreads();
  for (int s=DD/2; s>0; s>>=1){ if (d < s) sred[d] += sred[d+s]; __syncthreads(); }
  float m = sred[0]/(float)DD; __syncthreads();
  float diff = acc - m;
  sred[d] = diff*diff; __syncthreads();
  for (int s=DD/2; s>0; s>>=1){ if (d < s) sred[d] += sred[d+s]; __syncthreads(); }
  float var = sred[0]/(float)DD;
  d_icd[j*DD + d] = diff*rsqrtf(var + 1e-5f)*g[d] + b[d];
}

// ---------------- EW = X @ W (tiled, 16 rows per block) --------------------------
__global__ void k_gemm(const float* __restrict__ Xin, const float* __restrict__ W, int which){
  const float* X = (which == 2) ? d_icd : Xin;
  float* O = (which == 0) ? d_EWh : (which == 1) ? d_EWc : d_IWi;
  __shared__ float xs[16][DD];
  int r0 = blockIdx.x*16;
  for (int t=threadIdx.x; t<16*DD; t+=256)
    xs[t/DD][t%DD] = X[(size_t)(r0 + t/DD)*DD + (t%DD)];
  __syncthreads();
  float acc[16];
  #pragma unroll
  for (int r=0;r<16;r++) acc[r]=0.f;
  for (int k=0; k<DD; k++){
    float w = W[(size_t)k*HD + threadIdx.x];
    #pragma unroll
    for (int r=0;r<16;r++) acc[r] += xs[r][k]*w;
  }
  #pragma unroll
  for (int r=0;r<16;r++) O[(size_t)(r0+r)*HD + threadIdx.x] = acc[r];
}

// ---------------- per-patient masks / degrees / compact lists -------------------
__global__ void k_setup(const float* __restrict__ cx, const int* __restrict__ lens){
  int b = blockIdx.x;
  int len = lens[b];
  const float* cxb = cx + (size_t)b*EV*NC;
  for (int i=threadIdx.x; i<NC; i+=blockDim.x){
    unsigned m = 0; int c = 0;
    for (int e=0; e<len; e++){
      if (cxb[(size_t)e*NC + i] != 0.f){ m |= (1u<<e); c++; }
    }
    d_vmask[b*NC+i] = m;
    d_Dv[b*NC+i]    = (float)c;
    d_Dvinv[b*NC+i] = rsqrtf(fmaxf((float)c, EPSF));
    unsigned lowm = (1u << (len-1)) - 1u;   // bits t = 0..len-2
    d_smask[b*NC+i] = m & lowm;
    d_dmask[b*NC+i] = (m >> 1) & lowm;
  }
  __syncthreads();
  if (threadIdx.x < 32){
    int lane = threadIdx.x;
    int na=0, ns=0, nt=0;
    for (int base=0; base<NC; base+=32){
      int i = base + lane;
      bool va = (i<NC) && (d_Dv[b*NC+i] > 0.f);
      bool vs = (i<NC) && (d_smask[b*NC+i] != 0u);
      bool vt = (i<NC) && (d_dmask[b*NC+i] != 0u);
      unsigned ma=__ballot_sync(0xffffffffu,va);
      unsigned ms=__ballot_sync(0xffffffffu,vs);
      unsigned mt=__ballot_sync(0xffffffffu,vt);
      unsigned lt = (1u<<lane)-1u;
      if (va) d_act[b*NC + na + __popc(ma&lt)] = i;
      if (vs) d_Sl [b*NC + ns + __popc(ms&lt)] = i;
      if (vt) d_Tl [b*NC + nt + __popc(mt&lt)] = i;
      na += __popc(ma); ns += __popc(ms); nt += __popc(mt);
    }
    if (lane==0){ d_actn[b]=na; d_Sn[b]=ns; d_Tn[b]=nt; }
  }
}

// -------- t'[e] = invDe * sum_{i in visit e} Dvinv_i * (X@W)[i]  (both hyper branches)
__global__ void k_tprime(const int* __restrict__ lens){
  int b = blockIdx.x, e = blockIdx.y, d = threadIdx.x;
  float acch=0.f, acci=0.f, de=0.f;
  if (e < lens[b]){
    for (int i=0; i<NC; i++){
      unsigned m = d_vmask[b*NC+i];
      if ((m>>e) & 1u){
        float w = d_Dvinv[b*NC+i];
        acch += w * d_EWh[(size_t)i*HD + d];
        acci += w * d_IWi[(size_t)i*HD + d];
        de += 1.f;
      }
    }
  }
  float inv = 1.f / fmaxf(de, EPSF);
  d_tph[((size_t)b*EV+e)*HD + d] = acch*inv;
  d_tpi[((size_t)b*EV+e)*HD + d] = acci*inv;
}

// -------- row/col degree sums of binary transition matrix A ---------------------
__global__ void k_rowcol(){
  __shared__ int      sTi[NC];
  __shared__ unsigned sTd[NC];
  int b = blockIdx.x;
  int Tn = d_Tn[b], Sn = d_Sn[b];
  for (int q=threadIdx.x; q<Tn; q+=blockDim.x){
    int j = d_Tl[b*NC+q];
    sTi[q] = j; sTd[q] = d_dmask[b*NC+j];
  }
  __syncthreads();
  for (int p = blockIdx.y*blockDim.x + threadIdx.x; p < Sn; p += gridDim.y*blockDim.x){
    int i = d_Sl[b*NC+p];
    unsigned sm = d_smask[b*NC+i];
    float rs = 0.f;
    for (int q=0; q<Tn; q++){
      if ((sm & sTd[q]) && sTi[q] != i){
        rs += 1.f;
        atomicAdd(&d_colsum[b*NC + sTi[q]], 1.f);  // exact integer float -> deterministic
      }
    }
    d_rowsum[b*NC+i] = rs;
  }
}

// -------- pass1: yw[i] = rinv_i * sum_{j hit} cinv_j * EWc[j]  (i in S) ---------
__global__ void k_pass1(){
  __shared__ int      sTi[NC];
  __shared__ unsigned sTd[NC];
  __shared__ float    sTc[NC];
  int b = blockIdx.x, p = blockIdx.y;
  if (p >= d_Sn[b]) return;
  int Tn = d_Tn[b];
  for (int q=threadIdx.x; q<Tn; q+=blockDim.x){
    int j = d_Tl[b*NC+q];
    sTi[q] = j; sTd[q] = d_dmask[b*NC+j];
    sTc[q] = rsqrtf(fmaxf(d_colsum[b*NC+j], EPSF));
  }
  __syncthreads();
  int i = d_Sl[b*NC+p];
  unsigned sm = d_smask[b*NC+i];
  int d = threadIdx.x;
  float acc = 0.f;
  for (int q=0; q<Tn; q++){
    if ((sm & sTd[q]) && sTi[q] != i)
      acc += sTc[q] * d_EWc[(size_t)sTi[q]*HD + d];
  }
  float rinv = rsqrtf(fmaxf(d_rowsum[b*NC+i], EPSF));
  d_yw[((size_t)b*NC + p)*HD + d] = rinv*acc;
}

// -------- pass2: zr[j] = relu(cinv_j * sum_{i hit} rinv_i * yw[i] + b_c) --------
__global__ void k_pass2(const float* __restrict__ b_c){
  __shared__ int      sSi[NC];
  __shared__ unsigned sSs[NC];
  __shared__ float    sSr[NC];
  int b = blockIdx.x, q = blockIdx.y;
  if (q >= d_Tn[b]) return;
  int Sn = d_Sn[b];
  for (int p=threadIdx.x; p<Sn; p+=blockDim.x){
    int i = d_Sl[b*NC+p];
    sSi[p] = i; sSs[p] = d_smask[b*NC+i];
    sSr[p] = rsqrtf(fmaxf(d_rowsum[b*NC+i], EPSF));
  }
  __syncthreads();
  int j = d_Tl[b*NC+q];
  unsigned dm = d_dmask[b*NC+j];
  int d = threadIdx.x;
  float acc = 0.f;
  for (int p=0; p<Sn; p++){
    if ((sSs[p] & dm) && sSi[p] != j)
      acc += sSr[p] * d_yw[((size_t)b*NC + p)*HD + d];
  }
  float cinv = rsqrtf(fmaxf(d_colsum[b*NC+j], EPSF));
  d_zr[((size_t)b*NC + q)*HD + d] = fmaxf(cinv*acc + b_c[d], 0.f);
}

// -------- pooled branch embeddings (fixed order -> deterministic) ----------------
__global__ void k_pool(const float* __restrict__ b_h, const float* __restrict__ b_i,
                       const float* __restrict__ b_c){
  int b = blockIdx.x, d = threadIdx.x;
  int actn = d_actn[b], Tn = d_Tn[b];
  float bh = b_h[d], bi = b_i[d], bc = b_c[d];
  float ah = 0.f, ai = 0.f;
  for (int p=0; p<actn; p++){
    int i = d_act[b*NC+p];
    unsigned m = d_vmask[b*NC+i];
    float w = d_Dvinv[b*NC+i];
    float sh=0.f, si=0.f;
    while (m){
      int e = __ffs(m) - 1; m &= (m-1u);
      sh += d_tph[((size_t)b*EV+e)*HD + d];
      si += d_tpi[((size_t)b*EV+e)*HD + d];
    }
    ah += fmaxf(w*sh + bh, 0.f);
    ai += fmaxf(w*si + bi, 0.f);
  }
  float ac = 0.f;
  for (int q=0; q<Tn; q++) ac += d_zr[((size_t)b*NC + q)*HD + d];
  ac += (float)(actn - Tn) * fmaxf(bc, 0.f);   // active nodes with zero causal row
  float denom = fmaxf((float)actn, 1.f);
  d_eh[b*HD+d] = ah/denom;
  d_ec[b*HD+d] = ac/denom;
  d_ei[b*HD+d] = ai/denom;
}

// -------- gated residual -----------------------------------------------------------
__global__ void k_gates(const float* gwh, const float* gbh, const float* gwc,
                        const float* gbc, const float* gwi, const float* gbi){
  __shared__ float sr[HD];
  int b = blockIdx.x, d = threadIdx.x;
  float eh = d_eh[b*HD+d], ec = d_ec[b*HD+d], ei = d_ei[b*HD+d];
  float sh, sc, si;
  sr[d] = eh*gwh[d]; __syncthreads();
  for (int s=HD/2; s>0; s>>=1){ if (d<s) sr[d]+=sr[d+s]; __syncthreads(); }
  sh = sr[0]; __syncthreads();
  sr[d] = ec*gwc[d]; __syncthreads();
  for (int s=HD/2; s>0; s>>=1){ if (d<s) sr[d]+=sr[d+s]; __syncthreads(); }
  sc = sr[0]; __syncthreads();
  sr[d] = ei*gwi[d]; __syncthreads();
  for (int s=HD/2; s>0; s>>=1){ if (d<s) sr[d]+=sr[d+s]; __syncthreads(); }
  si = sr[0];
  float gh = 1.f/(1.f+expf(-(sh+gbh[0])));
  float gc = 1.f/(1.f+expf(-(sc+gbc[0])));
  float gi = 1.f/(1.f+expf(-(si+gbi[0])));
  d_res[b*HD+d] = gh*eh + gc*ec + gi*ei;
}

// -------- classifier ---------------------------------------------------------------
__global__ void k_cls(const float* __restrict__ Wc, const float* __restrict__ bc,
                      float* __restrict__ out){
  __shared__ float sres[HD];
  int b = blockIdx.x;
  int o = blockIdx.y*blockDim.x + threadIdx.x;
  for (int t=threadIdx.x; t<HD; t+=blockDim.x) sres[t] = d_res[b*HD+t];
  __syncthreads();
  if (o < NOUT){
    float acc = bc[o];
    for (int k=0; k<HD; k++) acc += sres[k]*Wc[(size_t)k*NOUT + o];
    out[(size_t)b*NOUT + o] = acc;
  }
}

// -------- InfoNCE loss (single block) ----------------------------------------------
__global__ void k_nce(float* __restrict__ out, int out_size){
  __shared__ float snorm[48];
  __shared__ float sE[256];
  int tid = threadIdx.x, wid = tid>>5, lane = tid&31;
  for (int row=wid; row<48; row+=8){
    const float* base = (row<16) ? (d_eh + row*HD)
                      : (row<32) ? (d_ec + (row-16)*HD)
                                 : (d_ei + (row-32)*HD);
    float s = 0.f;
    for (int d=lane; d<HD; d+=32){ float v = base[d]; s += v*v; }
    s = warp_sum(s);
    if (lane==0) snorm[row] = fmaxf(sqrtf(s), EPSF);
  }
  __syncthreads();
  float total = 0.f;
  for (int pair=0; pair<2; pair++){
    const float* Bm = pair ? d_ei : d_ec;
    int boff = pair ? 32 : 16;
    for (int idx=wid; idx<256; idx+=8){
      int i = idx>>4, j = idx&15;
      const float* a  = d_eh + i*HD;
      const float* bb = Bm   + j*HD;
      float s = 0.f;
      for (int d=lane; d<HD; d+=32) s += a[d]*bb[d];
      s = warp_sum(s);
      if (lane==0) sE[idx] = expf(s / (snorm[i]*snorm[boff+j]*0.4f));
    }
    __syncthreads();
    if (tid==0){
      float l = 0.f;
      for (int i=0;i<16;i++){
        float neg = 0.f;
        for (int j=0;j<16;j++) neg += sE[i*16+j];
        float pos = sE[i*16+i];
        l += -logf(pos/(neg + 1e-8f) + 1e-8f);
      }
      total += l/16.f;
    }
    __syncthreads();
  }
  if (tid==0 && out_size > NB*NOUT) out[NB*NOUT] = total;
}

// ==================================================================================
extern "C" void kernel_launch(void* const* d_in, const int* in_sizes, int n_in,
                              void* d_out, int out_size){
  (void)in_sizes; (void)n_in;
  const float* code_x = (const float*)d_in[0];
  const int*   lens   = (const int*)  d_in[1];
  const float* emb    = (const float*)d_in[2];
  const float* adj    = (const float*)d_in[3];
  const float* ln_g   = (const float*)d_in[4];
  const float* ln_b   = (const float*)d_in[5];
  const float* W_h    = (const float*)d_in[6];
  const float* b_h    = (const float*)d_in[7];
  const float* W_c    = (const float*)d_in[8];
  const float* b_c    = (const float*)d_in[9];
  const float* W_i    = (const float*)d_in[10];
  const float* b_i    = (const float*)d_in[11];
  const float* gw_h   = (const float*)d_in[12];
  const float* gb_h   = (const float*)d_in[13];
  const float* gw_c   = (const float*)d_in[14];
  const float* gb_c   = (const float*)d_in[15];
  const float* gw_i   = (const float*)d_in[16];
  const float* gb_i   = (const float*)d_in[17];
  const float* W_cls  = (const float*)d_in[18];
  const float* b_cls  = (const float*)d_in[19];
  float* out = (float*)d_out;

  k_init<<<(NB*NC + 255)/256, 256>>>();
  k_csr_rows<<<(NC + 31)/32, 1024>>>(adj);
  k_csr_cols<<<(NC + 255)/256, 256>>>(adj);

  // icd_conv: 3x [ adj.T @ (adj @ x) -> LN ]
  k_spmm_rows<<<NC, DD>>>(emb, 0);
  k_spmm_cols_ln<<<NC, DD>>>(ln_g, ln_b);
  k_spmm_rows<<<NC, DD>>>(emb, 1);
  k_spmm_cols_ln<<<NC, DD>>>(ln_g, ln_b);
  k_spmm_rows<<<NC, DD>>>(emb, 1);
  k_spmm_cols_ln<<<NC, DD>>>(ln_g, ln_b);

  // precompute X @ W for the three branches
  k_gemm<<<NC/16, 256>>>(emb, W_h, 0);
  k_gemm<<<NC/16, 256>>>(emb, W_c, 1);
  k_gemm<<<NC/16, 256>>>(emb, W_i, 2);   // uses d_icd internally

  k_setup<<<NB, 256>>>(code_x, lens);
  k_tprime<<<dim3(NB, EV), HD>>>(lens);
  k_rowcol<<<dim3(NB, 8), 256>>>();
  k_pass1<<<dim3(NB, NC), HD>>>();
  k_pass2<<<dim3(NB, NC), HD>>>(b_c);
  k_pool<<<NB, HD>>>(b_h, b_i, b_c);
  k_gates<<<NB, HD>>>(gw_h, gb_h, gw_c, gb_c, gw_i, gb_i);
  k_cls<<<dim3(NB, (NOUT + 255)/256), 256>>>(W_cls, b_cls, out);
  k_nce<<<1, 256>>>(out, out_size);
}